// round 5
// baseline (speedup 1.0000x reference)
#include <cuda_runtime.h>
#include <cuda_bf16.h>
#include <math.h>
#include <stdint.h>

// ---------------------------------------------------------------------------
// SparseMoE on GB300 (sm_103a)
//   hidden_states [4,1024,1024] f32, gate_w [1024,8] f32,
//   w1 [8,1024,4096] f32, w2 [8,4096,1024] f32
//   out = top2-routed MLP output [4,1024,1024] f32 (+ router_logits [4096,8])
//
// Pipeline (deterministic, graph-capturable, allocation-free):
//   1) router_kernel : logits + softmax + top2 + renorm weights (fp32 exact)
//   2) scan_kernel   : deterministic expert compaction (Hillis-Steele scan)
//   3) moe_gemm<1>   : h1 = gelu(x_gathered @ w1[e])     (tf32 mma.sync)
//   4) moe_gemm<2>   : y  = w * (h1 @ w2[e]) -> per (token,slot) row
//   5) combine_kernel: out[t] = y[2t] + y[2t+1]
//
// R5 fix: device scratch (g_h1/g_ypair) is now referenced ONLY from device
// code. R4 passed __device__ symbols as host-side kernel arguments, which
// resolves to the host shadow address -> illegal device address -> dead
// context -> poisoned output (rel_err exactly 1.0).
// ---------------------------------------------------------------------------

#define HIDDEN 1024
#define INTER  4096
#define NEXP   8
#define TOPK   2
#define MAXT   4096          // tokens (4*1024)
#define MAXPAIRS (MAXT*TOPK) // 8192

// ---- device scratch (no cudaMalloc allowed) ----
__device__ int2   g_tsel[MAXT];          // per-token selected experts (e0,e1)
__device__ float2 g_tw[MAXT];            // per-token normalized weights
__device__ int    g_rowtok[MAXPAIRS];    // compact row -> token*2+slot
__device__ float  g_roww[MAXPAIRS];      // compact row -> routing weight
__device__ int    g_count[NEXP];
__device__ int    g_offset[NEXP];
__device__ float  g_h1[(size_t)MAXPAIRS * INTER];     // 128 MiB
__device__ float  g_ypair[(size_t)MAXPAIRS * HIDDEN]; // 32 MiB

// ---------------------------------------------------------------------------
// helpers
// ---------------------------------------------------------------------------
__device__ __forceinline__ uint32_t f2tf32(float f) {
    uint32_t r;
    asm("cvt.rna.tf32.f32 %0, %1;" : "=r"(r) : "f"(f));
    return r;
}

__device__ __forceinline__ void mma_tf32(float c[4],
                                         const uint32_t a[4],
                                         const uint32_t b[2]) {
    asm volatile(
        "mma.sync.aligned.m16n8k8.row.col.f32.tf32.tf32.f32 "
        "{%0,%1,%2,%3}, {%4,%5,%6,%7}, {%8,%9}, {%0,%1,%2,%3};\n"
        : "+f"(c[0]), "+f"(c[1]), "+f"(c[2]), "+f"(c[3])
        : "r"(a[0]), "r"(a[1]), "r"(a[2]), "r"(a[3]),
          "r"(b[0]), "r"(b[1]));
}

__device__ __forceinline__ float gelu_exact(float x) {
    return 0.5f * x * (1.0f + erff(x * 0.70710678118654752f));
}

// ---------------------------------------------------------------------------
// 1) router: logits, softmax, top2, renormalized weights
//    one block per token, 256 threads = 8 experts x 32 lanes
// ---------------------------------------------------------------------------
__global__ void router_kernel(const float* __restrict__ x,
                              const float* __restrict__ gw,
                              float* __restrict__ out_logits,
                              int write_logits) {
    int t = blockIdx.x;
    __shared__ float sx[HIDDEN];
    __shared__ float slog[NEXP];

    int tid = threadIdx.x;
    // load token row (1024 floats, 256 threads x float4)
    ((float4*)sx)[tid] = ((const float4*)(x + (size_t)t * HIDDEN))[tid];
    __syncthreads();

    int e = tid >> 5;
    int lane = tid & 31;
    float acc = 0.f;
    #pragma unroll 8
    for (int i = lane; i < HIDDEN; i += 32)
        acc += sx[i] * gw[i * NEXP + e];
    #pragma unroll
    for (int o = 16; o > 0; o >>= 1)
        acc += __shfl_down_sync(0xffffffffu, acc, o);
    if (lane == 0) slog[e] = acc;
    __syncthreads();

    if (tid == 0) {
        float l[NEXP];
        float m = -1e30f;
        #pragma unroll
        for (int i = 0; i < NEXP; i++) { l[i] = slog[i]; m = fmaxf(m, l[i]); }
        float p[NEXP];
        #pragma unroll
        for (int i = 0; i < NEXP; i++) p[i] = __expf(l[i] - m);
        // top-2 (first index wins ties, matching lax.top_k)
        int i1 = 0;
        #pragma unroll
        for (int i = 1; i < NEXP; i++) if (p[i] > p[i1]) i1 = i;
        int i2 = (i1 == 0) ? 1 : 0;
        #pragma unroll
        for (int i = 0; i < NEXP; i++)
            if (i != i1 && p[i] > p[i2]) i2 = i;
        float s = p[i1] + p[i2];
        g_tsel[t] = make_int2(i1, i2);
        g_tw[t]   = make_float2(p[i1] / s, p[i2] / s);
    }
    if (write_logits && tid < NEXP)
        out_logits[(size_t)t * NEXP + tid] = slog[tid];
}

// ---------------------------------------------------------------------------
// 2) deterministic compaction: one block of 1024 threads, Hillis-Steele scan
//    (no atomics -> bit-deterministic row order, stable fp results)
// ---------------------------------------------------------------------------
__global__ void scan_kernel(int T) {
    __shared__ int s[1024 * NEXP];
    __shared__ int s_off[NEXP];
    int tid = threadIdx.x;
    int tp = T / 1024;       // tokens per thread (4)
    int t0 = tid * tp;

    int loc[NEXP];
    #pragma unroll
    for (int e = 0; e < NEXP; e++) loc[e] = 0;

    int2  sel[4];
    float2 wt[4];
    for (int j = 0; j < tp; j++) {
        sel[j] = g_tsel[t0 + j];
        wt[j]  = g_tw[t0 + j];
        loc[sel[j].x]++;
        loc[sel[j].y]++;
    }

    int val[NEXP];
    #pragma unroll
    for (int e = 0; e < NEXP; e++) { val[e] = loc[e]; s[tid * NEXP + e] = val[e]; }

    for (int off = 1; off < 1024; off <<= 1) {
        __syncthreads();
        int add[NEXP];
        #pragma unroll
        for (int e = 0; e < NEXP; e++)
            add[e] = (tid >= off) ? s[(tid - off) * NEXP + e] : 0;
        __syncthreads();
        #pragma unroll
        for (int e = 0; e < NEXP; e++) { val[e] += add[e]; s[tid * NEXP + e] = val[e]; }
    }
    __syncthreads();

    if (tid == 0) {
        int o = 0;
        for (int e = 0; e < NEXP; e++) {
            int tot = s[1023 * NEXP + e];
            g_count[e]  = tot;
            g_offset[e] = o;
            s_off[e]    = o;
            o += tot;
        }
    }
    __syncthreads();

    int pos[NEXP];
    #pragma unroll
    for (int e = 0; e < NEXP; e++) pos[e] = s_off[e] + (val[e] - loc[e]);

    for (int j = 0; j < tp; j++) {
        int t = t0 + j;
        int e0 = sel[j].x, e1 = sel[j].y;
        int i0 = pos[e0]++;
        g_rowtok[i0] = t * 2;     g_roww[i0] = wt[j].x;
        int i1 = pos[e1]++;
        g_rowtok[i1] = t * 2 + 1; g_roww[i1] = wt[j].y;
    }
}

// ---------------------------------------------------------------------------
// 3/4) grouped GEMM, tf32 mma.sync m16n8k8
//   tile 128x128x32, 256 threads = 8 warps (2 m x 4 n), warp tile 64x32
//   MODE 1: A = x gathered rows (param), epilogue gelu -> g_h1
//   MODE 2: A = g_h1 rows (device symbol), epilogue *w  -> g_ypair
//   Scratch pointers are resolved IN DEVICE CODE (the R4 bug fix).
// ---------------------------------------------------------------------------
template <int MODE>
__global__ __launch_bounds__(256, 1)
void moe_gemm(const float* __restrict__ Xglob,
              const float* __restrict__ Wglob,
              int K, int N) {
    const int e = blockIdx.z;
    const int count = g_count[e];
    const int m0 = blockIdx.y * 128;
    if (m0 >= count) return;
    const int off = g_offset[e];
    const int n0 = blockIdx.x * 128;
    const float* W = Wglob + (size_t)e * K * N;

    // device-side binding of scratch buffers (valid device addresses)
    const float* Aglob = (MODE == 1) ? Xglob : (const float*)g_h1;
    float*       Out   = (MODE == 1) ? (float*)g_h1 : (float*)g_ypair;

    __shared__ uint32_t As[128][36];   // [m][k], pitch 36 -> conflict-free frags
    __shared__ uint32_t Bs[32][132];   // [k][n], pitch 132

    const int tid = threadIdx.x;
    const int lane = tid & 31;
    const int warp = tid >> 5;
    const int wm = warp & 1;           // 2 warps in m
    const int wn = warp >> 1;          // 4 warps in n
    const int wrow = wm * 64;
    const int wcol = wn * 32;

    float c[4][4][4];
    #pragma unroll
    for (int i = 0; i < 4; i++)
        #pragma unroll
        for (int j = 0; j < 4; j++)
            #pragma unroll
            for (int r = 0; r < 4; r++) c[i][j][r] = 0.f;

    // A row pointers for this thread's 4 staging rows
    const float* arow[4];
    #pragma unroll
    for (int p = 0; p < 4; p++) {
        int r = (tid >> 3) + 32 * p;
        int gr = m0 + r;
        if (MODE == 1) {
            int info = (gr < count) ? g_rowtok[off + gr] : g_rowtok[off];
            arow[p] = Aglob + (size_t)(info >> 1) * K;
        } else {
            int rr = (gr < count) ? gr : (count - 1);
            arow[p] = Aglob + (size_t)(off + rr) * K;
        }
    }

    const int acol = (tid & 7) * 4;
    const int bk   = tid >> 3;
    const int nb   = (tid & 7) * 16;

    for (int k0 = 0; k0 < K; k0 += 32) {
        // stage A tile (convert to tf32 once)
        #pragma unroll
        for (int p = 0; p < 4; p++) {
            float4 v = *(const float4*)(arow[p] + k0 + acol);
            int r = (tid >> 3) + 32 * p;
            uint4 u = make_uint4(f2tf32(v.x), f2tf32(v.y), f2tf32(v.z), f2tf32(v.w));
            *(uint4*)&As[r][acol] = u;
        }
        // stage B tile (natural [k][n], coalesced)
        {
            const float* brow = W + (size_t)(k0 + bk) * N + n0 + nb;
            #pragma unroll
            for (int j = 0; j < 4; j++) {
                float4 v = *(const float4*)(brow + j * 4);
                uint4 u = make_uint4(f2tf32(v.x), f2tf32(v.y), f2tf32(v.z), f2tf32(v.w));
                *(uint4*)&Bs[bk][nb + j * 4] = u;
            }
        }
        __syncthreads();

        #pragma unroll
        for (int kk = 0; kk < 4; kk++) {
            const int kb = kk * 8;
            uint32_t a[4][4], b[4][2];
            #pragma unroll
            for (int im = 0; im < 4; im++) {
                int row = wrow + im * 16 + (lane >> 2);
                int kc = kb + (lane & 3);
                a[im][0] = As[row][kc];
                a[im][1] = As[row + 8][kc];
                a[im][2] = As[row][kc + 4];
                a[im][3] = As[row + 8][kc + 4];
            }
            #pragma unroll
            for (int jn = 0; jn < 4; jn++) {
                int n = wcol + jn * 8 + (lane >> 2);
                int kc = kb + (lane & 3);
                b[jn][0] = Bs[kc][n];
                b[jn][1] = Bs[kc + 4][n];
            }
            #pragma unroll
            for (int im = 0; im < 4; im++)
                #pragma unroll
                for (int jn = 0; jn < 4; jn++)
                    mma_tf32(c[im][jn], a[im], b[jn]);
        }
        __syncthreads();
    }

    // epilogue
    #pragma unroll
    for (int im = 0; im < 4; im++) {
        #pragma unroll
        for (int half = 0; half < 2; half++) {
            int m = wrow + im * 16 + (lane >> 2) + 8 * half;
            int gr = m0 + m;
            if (gr >= count) continue;
            size_t base;
            float wgt = 1.f;
            if (MODE == 1) {
                base = (size_t)(off + gr) * N;
            } else {
                int info = g_rowtok[off + gr];
                wgt = g_roww[off + gr];
                base = (size_t)info * N;
            }
            #pragma unroll
            for (int jn = 0; jn < 4; jn++) {
                int n = n0 + wcol + jn * 8 + (lane & 3) * 2;
                float v0 = c[im][jn][half * 2];
                float v1 = c[im][jn][half * 2 + 1];
                float2 o;
                if (MODE == 1) { o.x = gelu_exact(v0); o.y = gelu_exact(v1); }
                else           { o.x = wgt * v0;       o.y = wgt * v1; }
                *(float2*)(Out + base + n) = o;
            }
        }
    }
}

// ---------------------------------------------------------------------------
// 5) combine: out[t] = y[2t] + y[2t+1]   (deterministic, vectorized)
// ---------------------------------------------------------------------------
__global__ void combine_kernel(float* __restrict__ out, int T) {
    size_t i = (size_t)blockIdx.x * blockDim.x + threadIdx.x; // float4 index
    size_t total = (size_t)T * (HIDDEN / 4);
    if (i >= total) return;
    size_t t = i / (HIDDEN / 4);
    size_t h4 = i % (HIDDEN / 4);
    const float4* yp = (const float4*)g_ypair;
    float4 a = yp[(t * 2) * (HIDDEN / 4) + h4];
    float4 b = yp[(t * 2 + 1) * (HIDDEN / 4) + h4];
    float4 o;
    o.x = a.x + b.x; o.y = a.y + b.y; o.z = a.z + b.z; o.w = a.w + b.w;
    ((float4*)out)[i] = o;
}

// ---------------------------------------------------------------------------
extern "C" void kernel_launch(void* const* d_in, const int* in_sizes, int n_in,
                              void* d_out, int out_size) {
    const float* x  = (const float*)d_in[0];  // [T, H]
    const float* gw = (const float*)d_in[1];  // [H, E]
    const float* w1 = (const float*)d_in[2];  // [E, H, I]
    const float* w2 = (const float*)d_in[3];  // [E, I, H]
    float* out = (float*)d_out;

    const int T = in_sizes[0] / HIDDEN;       // 4096

    // output layout: [out (T*H)] optionally followed by [router_logits (T*E)]
    int write_logits = (out_size >= T * HIDDEN + T * NEXP) ? 1 : 0;
    float* logits_ptr = out + (size_t)T * HIDDEN;

    // 1) router
    router_kernel<<<T, 256>>>(x, gw, logits_ptr, write_logits);

    // 2) deterministic compaction
    scan_kernel<<<1, 1024>>>(T);

    // 3) GEMM1: h1 = gelu(x_g @ w1[e])   [rows, INTER], K=HIDDEN
    {
        dim3 grid(INTER / 128, (T + 127) / 128, NEXP);
        moe_gemm<1><<<grid, 256>>>(x, w1, HIDDEN, INTER);
    }

    // 4) GEMM2: y = w * (h1 @ w2[e])     [rows, HIDDEN], K=INTER
    {
        dim3 grid(HIDDEN / 128, (T + 127) / 128, NEXP);
        moe_gemm<2><<<grid, 256>>>(nullptr, w2, INTER, HIDDEN);
    }

    // 5) combine
    {
        size_t total = (size_t)T * (HIDDEN / 4);
        int blocks = (int)((total + 255) / 256);
        combine_kernel<<<blocks, 256>>>(out, T);
    }
}

// round 6
// speedup vs baseline: 1.9038x; 1.9038x over previous
#include <cuda_runtime.h>
#include <math.h>
#include <stdint.h>

// ---------------------------------------------------------------------------
// SparseMoE on GB300 (sm_103a) — R6
//   R5 (passed, 1980us): single-buffered tf32 mma.sync, L1 53% / tensor 23%.
//   R6: 3-stage cp.async pipeline, 128x256 CTA tile (64x64 warp tiles),
//       conflict-free smem (pitches == 8 mod 32), A pre-converted to tf32
//       with k-pair permutation enabling LDS.64 fragment loads.
//
// Pipeline:
//   1) router_kernel : logits + softmax + top2 + renorm (fp32 exact)
//   2) scan_kernel   : deterministic expert compaction (no atomics)
//   3) xprep_kernel  : g_xt = tf32(x), k-pair-permuted
//   4) moe_gemm<1>   : h1 = tf32(gelu(x_g @ w1[e])), permuted  (tf32 mma)
//   5) moe_gemm<2>   : y  = w * (h1 @ w2[e])
//   6) combine_kernel: out[t] = y[2t] + y[2t+1]
// ---------------------------------------------------------------------------

#define HIDDEN 1024
#define INTER  4096
#define NEXP   8
#define MAXT   4096
#define MAXPAIRS (MAXT*2)

// GEMM tiling
#define TM 128
#define TN 256
#define TK 32
#define APITCH 40     // u32 pitch; 40 % 32 == 8 -> conflict-free A frags
#define BPITCH 264    // u32 pitch; 264 % 32 == 8 -> conflict-free B frags
#define ABYTES (TM*APITCH*4)          // 20480
#define BBYTES (TK*BPITCH*4)          // 33792
#define STAGE_BYTES (ABYTES+BBYTES)   // 54272
#define NSTAGE 3                      // 162816 B dynamic smem

// ---- device scratch (no cudaMalloc allowed) ----
__device__ int2   g_tsel[MAXT];
__device__ float2 g_tw[MAXT];
__device__ int    g_rowtok[MAXPAIRS];
__device__ float  g_roww[MAXPAIRS];
__device__ int    g_count[NEXP];
__device__ int    g_offset[NEXP];
__device__ float  g_xt[(size_t)MAXT * HIDDEN];        // tf32 bits, k-permuted
__device__ float  g_h1[(size_t)MAXPAIRS * INTER];     // tf32 bits, k-permuted
__device__ float  g_ypair[(size_t)MAXPAIRS * HIDDEN];

// ---------------------------------------------------------------------------
// helpers
// ---------------------------------------------------------------------------
__device__ __forceinline__ uint32_t f2tf32(float f) {
    uint32_t r;
    asm("cvt.rna.tf32.f32 %0, %1;" : "=r"(r) : "f"(f));
    return r;
}

__device__ __forceinline__ void mma_tf32(float c[4],
                                         const uint32_t a[4],
                                         const uint32_t b[2]) {
    asm volatile(
        "mma.sync.aligned.m16n8k8.row.col.f32.tf32.tf32.f32 "
        "{%0,%1,%2,%3}, {%4,%5,%6,%7}, {%8,%9}, {%0,%1,%2,%3};\n"
        : "+f"(c[0]), "+f"(c[1]), "+f"(c[2]), "+f"(c[3])
        : "r"(a[0]), "r"(a[1]), "r"(a[2]), "r"(a[3]),
          "r"(b[0]), "r"(b[1]));
}

__device__ __forceinline__ float gelu_exact(float x) {
    return 0.5f * x * (1.0f + erff(x * 0.70710678118654752f));
}

__device__ __forceinline__ void cp16(uint32_t dst, const void* src) {
    asm volatile("cp.async.cg.shared.global [%0], [%1], 16;\n"
                 :: "r"(dst), "l"(src));
}
__device__ __forceinline__ void cp_commit() {
    asm volatile("cp.async.commit_group;\n");
}
template <int N> __device__ __forceinline__ void cp_wait() {
    asm volatile("cp.async.wait_group %0;\n" :: "n"(N));
}

// ---------------------------------------------------------------------------
// 1) router
// ---------------------------------------------------------------------------
__global__ void router_kernel(const float* __restrict__ x,
                              const float* __restrict__ gw,
                              float* __restrict__ out_logits,
                              int write_logits) {
    int t = blockIdx.x;
    __shared__ float sx[HIDDEN];
    __shared__ float slog[NEXP];

    int tid = threadIdx.x;
    ((float4*)sx)[tid] = ((const float4*)(x + (size_t)t * HIDDEN))[tid];
    __syncthreads();

    int e = tid >> 5;
    int lane = tid & 31;
    float acc = 0.f;
    #pragma unroll 8
    for (int i = lane; i < HIDDEN; i += 32)
        acc += sx[i] * gw[i * NEXP + e];
    #pragma unroll
    for (int o = 16; o > 0; o >>= 1)
        acc += __shfl_down_sync(0xffffffffu, acc, o);
    if (lane == 0) slog[e] = acc;
    __syncthreads();

    if (tid == 0) {
        float l[NEXP];
        float m = -1e30f;
        #pragma unroll
        for (int i = 0; i < NEXP; i++) { l[i] = slog[i]; m = fmaxf(m, l[i]); }
        float p[NEXP];
        #pragma unroll
        for (int i = 0; i < NEXP; i++) p[i] = __expf(l[i] - m);
        int i1 = 0;
        #pragma unroll
        for (int i = 1; i < NEXP; i++) if (p[i] > p[i1]) i1 = i;
        int i2 = (i1 == 0) ? 1 : 0;
        #pragma unroll
        for (int i = 0; i < NEXP; i++)
            if (i != i1 && p[i] > p[i2]) i2 = i;
        float s = p[i1] + p[i2];
        g_tsel[t] = make_int2(i1, i2);
        g_tw[t]   = make_float2(p[i1] / s, p[i2] / s);
    }
    if (write_logits && tid < NEXP)
        out_logits[(size_t)t * NEXP + tid] = slog[tid];
}

// ---------------------------------------------------------------------------
// 2) deterministic compaction (Hillis-Steele scan, no atomics)
// ---------------------------------------------------------------------------
__global__ void scan_kernel(int T) {
    __shared__ int s[1024 * NEXP];
    __shared__ int s_off[NEXP];
    int tid = threadIdx.x;
    int tp = T / 1024;
    int t0 = tid * tp;

    int loc[NEXP];
    #pragma unroll
    for (int e = 0; e < NEXP; e++) loc[e] = 0;

    int2  sel[4];
    float2 wt[4];
    for (int j = 0; j < tp; j++) {
        sel[j] = g_tsel[t0 + j];
        wt[j]  = g_tw[t0 + j];
        loc[sel[j].x]++;
        loc[sel[j].y]++;
    }

    int val[NEXP];
    #pragma unroll
    for (int e = 0; e < NEXP; e++) { val[e] = loc[e]; s[tid * NEXP + e] = val[e]; }

    for (int off = 1; off < 1024; off <<= 1) {
        __syncthreads();
        int add[NEXP];
        #pragma unroll
        for (int e = 0; e < NEXP; e++)
            add[e] = (tid >= off) ? s[(tid - off) * NEXP + e] : 0;
        __syncthreads();
        #pragma unroll
        for (int e = 0; e < NEXP; e++) { val[e] += add[e]; s[tid * NEXP + e] = val[e]; }
    }
    __syncthreads();

    if (tid == 0) {
        int o = 0;
        for (int e = 0; e < NEXP; e++) {
            int tot = s[1023 * NEXP + e];
            g_count[e]  = tot;
            g_offset[e] = o;
            s_off[e]    = o;
            o += tot;
        }
    }
    __syncthreads();

    int pos[NEXP];
    #pragma unroll
    for (int e = 0; e < NEXP; e++) pos[e] = s_off[e] + (val[e] - loc[e]);

    for (int j = 0; j < tp; j++) {
        int t = t0 + j;
        int e0 = sel[j].x, e1 = sel[j].y;
        int i0 = pos[e0]++;
        g_rowtok[i0] = t * 2;     g_roww[i0] = wt[j].x;
        int i1 = pos[e1]++;
        g_rowtok[i1] = t * 2 + 1; g_roww[i1] = wt[j].y;
    }
}

// ---------------------------------------------------------------------------
// 3) x-prep: tf32-convert + k-pair permute (within each 8-k block the order
//    is (0,4,1,5,2,6,3,7) so fragment pairs (k, k+4) are adjacent -> LDS.64)
// ---------------------------------------------------------------------------
__global__ void xprep_kernel(const float* __restrict__ x, int T) {
    int i = blockIdx.x * blockDim.x + threadIdx.x;   // 8-block index
    int total = T * (HIDDEN / 8);
    if (i >= total) return;
    const float4* src = (const float4*)x;
    float4 lo = src[i * 2];
    float4 hi = src[i * 2 + 1];
    float4 o0, o1;
    o0.x = __uint_as_float(f2tf32(lo.x)); o0.y = __uint_as_float(f2tf32(hi.x));
    o0.z = __uint_as_float(f2tf32(lo.y)); o0.w = __uint_as_float(f2tf32(hi.y));
    o1.x = __uint_as_float(f2tf32(lo.z)); o1.y = __uint_as_float(f2tf32(hi.z));
    o1.z = __uint_as_float(f2tf32(lo.w)); o1.w = __uint_as_float(f2tf32(hi.w));
    float4* dst = (float4*)g_xt;
    dst[i * 2]     = o0;
    dst[i * 2 + 1] = o1;
}

// ---------------------------------------------------------------------------
// 4/5) grouped GEMM, tf32 mma.sync, 128x256 tile, 3-stage cp.async
//   8 warps = 2m x 4n, warp tile 64x64.
//   A (activations): pre-converted tf32 bits, k-permuted -> LDS.64 frags.
//   B (weights): raw fp32 via cp.async, cvt to tf32 after LDS.
// ---------------------------------------------------------------------------
template <int MODE>
__global__ __launch_bounds__(256, 1)
void moe_gemm(const float* __restrict__ Wglob, int K, int N) {
    extern __shared__ char smem_raw[];
    const int e = blockIdx.z;
    const int count = g_count[e];
    const int m0 = blockIdx.y * TM;
    if (m0 >= count) return;
    const int off = g_offset[e];
    const int n0 = blockIdx.x * TN;
    const float* W = Wglob + (size_t)e * K * N;

    const float* Aglob = (MODE == 1) ? (const float*)g_xt : (const float*)g_h1;
    float*       Out   = (MODE == 1) ? (float*)g_h1 : (float*)g_ypair;

    const int tid  = threadIdx.x;
    const int lane = tid & 31;
    const int warp = tid >> 5;
    const int q    = lane & 3;     // k-quad within fragment
    const int lr   = lane >> 2;    // row/col lane group
    const int wrow = (warp & 1) * 64;
    const int wcol = (warp >> 1) * 64;

    const uint32_t sbase = (uint32_t)__cvta_generic_to_shared(smem_raw);

    // A source row pointers for this thread's 4 staged rows
    const float* arow[4];
    #pragma unroll
    for (int p = 0; p < 4; p++) {
        int r  = (tid >> 3) + 32 * p;
        int gr = m0 + r;
        int rr = (gr < count) ? gr : (count - 1);
        if (MODE == 1) {
            int tok = g_rowtok[off + rr] >> 1;
            arow[p] = Aglob + (size_t)tok * K;
        } else {
            arow[p] = Aglob + (size_t)(off + rr) * K;
        }
    }
    const int acol = (tid & 7) * 4;   // float offset of this thread's A chunk
    const int bk   = tid >> 3;        // B k-row
    const int bn   = (tid & 7) * 4;   // B base float col (chunks stride 32)

    auto issue_stage = [&](int ki) {
        const int s = ki % NSTAGE;
        const uint32_t sa = sbase + s * STAGE_BYTES;
        const uint32_t sb = sa + ABYTES;
        const int k0 = ki * TK;
        #pragma unroll
        for (int p = 0; p < 4; p++) {
            int r = (tid >> 3) + 32 * p;
            cp16(sa + (uint32_t)(r * APITCH + acol) * 4, arow[p] + k0 + acol);
        }
        const float* bsrc = W + (size_t)(k0 + bk) * N + n0 + bn;
        #pragma unroll
        for (int j = 0; j < 8; j++)
            cp16(sb + (uint32_t)(bk * BPITCH + bn + 32 * j) * 4, bsrc + 32 * j);
        cp_commit();
    };

    float c[4][8][4];
    #pragma unroll
    for (int i = 0; i < 4; i++)
        #pragma unroll
        for (int j = 0; j < 8; j++)
            #pragma unroll
            for (int r = 0; r < 4; r++) c[i][j][r] = 0.f;

    const int KI = K / TK;
    issue_stage(0);
    issue_stage(1);

    for (int i = 0; i < KI; i++) {
        cp_wait<1>();
        __syncthreads();
        if (i + 2 < KI) issue_stage(i + 2);

        const uint32_t* As = (const uint32_t*)(smem_raw + (i % NSTAGE) * STAGE_BYTES);
        const float*    Bs = (const float*)(smem_raw + (i % NSTAGE) * STAGE_BYTES + ABYTES);

        #pragma unroll
        for (int kk = 0; kk < 4; kk++) {
            const int kb = kk * 8;
            uint32_t a[4][4];
            #pragma unroll
            for (int im = 0; im < 4; im++) {
                int row = wrow + im * 16 + lr;
                uint2 v0 = *(const uint2*)&As[row * APITCH + kb + 2 * q];
                uint2 v1 = *(const uint2*)&As[(row + 8) * APITCH + kb + 2 * q];
                a[im][0] = v0.x; a[im][2] = v0.y;   // (k, k+4) adjacent (perm)
                a[im][1] = v1.x; a[im][3] = v1.y;
            }
            uint32_t b[8][2];
            #pragma unroll
            for (int jn = 0; jn < 8; jn++) {
                int nn = wcol + jn * 8 + lr;
                b[jn][0] = f2tf32(Bs[(kb + q) * BPITCH + nn]);
                b[jn][1] = f2tf32(Bs[(kb + q + 4) * BPITCH + nn]);
            }
            #pragma unroll
            for (int im = 0; im < 4; im++)
                #pragma unroll
                for (int jn = 0; jn < 8; jn++)
                    mma_tf32(c[im][jn], a[im], b[jn]);
        }
    }

    // epilogue
    #pragma unroll
    for (int im = 0; im < 4; im++) {
        #pragma unroll
        for (int half = 0; half < 2; half++) {
            int m  = wrow + im * 16 + lr + 8 * half;
            int gr = m0 + m;
            if (gr >= count) continue;
            if (MODE == 1) {
                // write tf32(gelu) in k-permuted layout for GEMM2's A path
                size_t base = (size_t)(off + gr) * N;
                int pos0 = (q & 1) * 4 + (q >> 1);   // perm(2q); perm(2q+1)=pos0+2
                #pragma unroll
                for (int jn = 0; jn < 8; jn++) {
                    int nb8 = n0 + wcol + jn * 8;
                    float v0 = gelu_exact(c[im][jn][half * 2]);
                    float v1 = gelu_exact(c[im][jn][half * 2 + 1]);
                    Out[base + nb8 + pos0]     = __uint_as_float(f2tf32(v0));
                    Out[base + nb8 + pos0 + 2] = __uint_as_float(f2tf32(v1));
                }
            } else {
                int info  = g_rowtok[off + gr];
                float wgt = g_roww[off + gr];
                size_t base = (size_t)info * N;
                #pragma unroll
                for (int jn = 0; jn < 8; jn++) {
                    int n = n0 + wcol + jn * 8 + q * 2;
                    float2 o;
                    o.x = wgt * c[im][jn][half * 2];
                    o.y = wgt * c[im][jn][half * 2 + 1];
                    *(float2*)(Out + base + n) = o;
                }
            }
        }
    }
}

// ---------------------------------------------------------------------------
// 6) combine: out[t] = y[2t] + y[2t+1]
// ---------------------------------------------------------------------------
__global__ void combine_kernel(float* __restrict__ out, int T) {
    size_t i = (size_t)blockIdx.x * blockDim.x + threadIdx.x;
    size_t total = (size_t)T * (HIDDEN / 4);
    if (i >= total) return;
    size_t t  = i / (HIDDEN / 4);
    size_t h4 = i % (HIDDEN / 4);
    const float4* yp = (const float4*)g_ypair;
    float4 a = yp[(t * 2) * (HIDDEN / 4) + h4];
    float4 b = yp[(t * 2 + 1) * (HIDDEN / 4) + h4];
    float4 o;
    o.x = a.x + b.x; o.y = a.y + b.y; o.z = a.z + b.z; o.w = a.w + b.w;
    ((float4*)out)[i] = o;
}

// ---------------------------------------------------------------------------
extern "C" void kernel_launch(void* const* d_in, const int* in_sizes, int n_in,
                              void* d_out, int out_size) {
    const float* x  = (const float*)d_in[0];
    const float* gw = (const float*)d_in[1];
    const float* w1 = (const float*)d_in[2];
    const float* w2 = (const float*)d_in[3];
    float* out = (float*)d_out;

    const int T = in_sizes[0] / HIDDEN;

    int write_logits = (out_size >= T * HIDDEN + T * NEXP) ? 1 : 0;
    float* logits_ptr = out + (size_t)T * HIDDEN;

    const int smem_bytes = NSTAGE * STAGE_BYTES;
    cudaFuncSetAttribute(moe_gemm<1>, cudaFuncAttributeMaxDynamicSharedMemorySize, smem_bytes);
    cudaFuncSetAttribute(moe_gemm<2>, cudaFuncAttributeMaxDynamicSharedMemorySize, smem_bytes);

    // 1) router
    router_kernel<<<T, 256>>>(x, gw, logits_ptr, write_logits);

    // 2) deterministic compaction
    scan_kernel<<<1, 1024>>>(T);

    // 3) x -> tf32, k-permuted
    {
        int total = T * (HIDDEN / 8);
        xprep_kernel<<<(total + 255) / 256, 256>>>(x, T);
    }

    // 4) GEMM1: h1 = tf32(gelu(x_g @ w1[e]))   K=HIDDEN, N=INTER
    {
        dim3 grid(INTER / TN, (T + TM - 1) / TM, NEXP);
        moe_gemm<1><<<grid, 256, smem_bytes>>>(w1, HIDDEN, INTER);
    }

    // 5) GEMM2: y = w * (h1 @ w2[e])           K=INTER, N=HIDDEN
    {
        dim3 grid(HIDDEN / TN, (T + TM - 1) / TM, NEXP);
        moe_gemm<2><<<grid, 256, smem_bytes>>>(w2, INTER, HIDDEN);
    }

    // 6) combine
    {
        size_t total = (size_t)T * (HIDDEN / 4);
        combine_kernel<<<(int)((total + 255) / 256), 256>>>(out, T);
    }
}